// round 8
// baseline (speedup 1.0000x reference)
#include <cuda_runtime.h>
#include <math.h>

namespace {

constexpr int B  = 64;
constexpr int T  = 256;
constexpr int IN = 512;
constexpr int H  = 1024;
constexpr int M  = B * T;   // 16384

constexpr int RGRID = 128;     // persistent blocks, each owns 8 N-columns
constexpr int RTHREADS = 512;  // 16 warps: tx(8) x tb(16) x kz(4)

typedef unsigned long long u64;

// Scratch (device globals — no allocation allowed)
__device__ float g_P[3][(size_t)M * H];   // masked input projections + bias: [f, o, c]
__device__ float g_h[2][H * B];           // h ping-pong, K-MAJOR: [n(H)][b(B)]

// grid barrier state
__device__ unsigned g_bar_count = 0;
__device__ volatile unsigned g_bar_gen = 0;

__device__ __forceinline__ u64 pack2(float v) {
    u64 r; asm("mov.b64 %0, {%1, %2};" : "=l"(r) : "f"(v), "f"(v)); return r;
}
__device__ __forceinline__ u64 pack_pair(float x, float y) {
    u64 r; asm("mov.b64 %0, {%1, %2};" : "=l"(r) : "f"(x), "f"(y)); return r;
}
__device__ __forceinline__ u64 fma2(u64 a, u64 b, u64 c) {
    u64 d; asm("fma.rn.f32x2 %0, %1, %2, %3;" : "=l"(d) : "l"(a), "l"(b), "l"(c)); return d;
}
__device__ __forceinline__ float2 unpack2(u64 v) {
    float2 f; asm("mov.b64 {%0, %1}, %2;" : "=f"(f.x), "=f"(f.y) : "l"(v)); return f;
}
__device__ __forceinline__ float sigmoidf_(float x) { return 1.0f / (1.0f + expf(-x)); }

__device__ __forceinline__ float4 ldcg4(const float* p) {
    float4 v;
    asm volatile("ld.global.cg.v4.f32 {%0,%1,%2,%3}, [%4];"
                 : "=f"(v.x), "=f"(v.y), "=f"(v.z), "=f"(v.w) : "l"(p));
    return v;
}

// All blocks are co-resident (1 block/SM via smem footprint, grid 128 <= 148 SMs).
__device__ __forceinline__ void grid_barrier() {
    __syncthreads();
    if (threadIdx.x == 0) {
        __threadfence();
        unsigned old = g_bar_gen;
        if (atomicAdd(&g_bar_count, 1u) == (unsigned)(gridDim.x - 1)) {
            g_bar_count = 0;
            __threadfence();
            g_bar_gen = old + 1;
        } else {
            while (g_bar_gen == old) { }
        }
        __threadfence();
    }
    __syncthreads();
}

// ---------------------------------------------------------------------------
// Input projection: P_g[m][n] = sigmoid(X[m]·Wm_g[n]) * (X[m]·W_g[n]) + b_g[n]
// GEMM M=16384, N=1024, K=512, two B-matrices per output. (unchanged)
// ---------------------------------------------------------------------------
constexpr int BM = 64, BN = 64, BK = 16;

__global__ __launch_bounds__(128)
void input_proj(const float* __restrict__ X,
                const float* __restrict__ W0, const float* __restrict__ Wm0, const float* __restrict__ b0,
                const float* __restrict__ W1, const float* __restrict__ Wm1, const float* __restrict__ b1,
                const float* __restrict__ W2, const float* __restrict__ Wm2, const float* __restrict__ b2)
{
    __shared__ __align__(16) float sX[BK][BM + 2];
    __shared__ __align__(16) float sW[BK][BN + 2];
    __shared__ __align__(16) float sM[BK][BN + 2];

    const int g = blockIdx.z;
    const float* Wg  = (g == 0) ? W0  : (g == 1) ? W1  : W2;
    const float* Wmg = (g == 0) ? Wm0 : (g == 1) ? Wm1 : Wm2;
    const float* bg  = (g == 0) ? b0  : (g == 1) ? b1  : b2;

    const int tid = threadIdx.x;
    const int tx = tid & 15;
    const int ty = tid >> 4;
    const int m_blk = blockIdx.y * BM;
    const int n_blk = blockIdx.x * BN;

    const float* Xb = X   + (size_t)m_blk * IN;
    const float* Wb = Wg  + (size_t)n_blk * IN;
    const float* Mb = Wmg + (size_t)n_blk * IN;

    u64 accW[4][4], accM[4][4];
    #pragma unroll
    for (int j = 0; j < 4; j++)
        #pragma unroll
        for (int i = 0; i < 4; i++) { accW[j][i] = 0ull; accM[j][i] = 0ull; }

    float4 xb[2], wb[2], mb[2];
    #pragma unroll
    for (int r = 0; r < 2; r++) {
        int idx = tid + r * 128;
        int row = idx >> 2, k4 = (idx & 3) << 2;
        size_t off = (size_t)row * IN + k4;
        xb[r] = *(const float4*)(Xb + off);
        wb[r] = *(const float4*)(Wb + off);
        mb[r] = *(const float4*)(Mb + off);
    }

    for (int k0 = 0; k0 < IN; k0 += BK) {
        #pragma unroll
        for (int r = 0; r < 2; r++) {
            int idx = tid + r * 128;
            int row = idx >> 2, k4 = (idx & 3) << 2;
            sX[k4 + 0][row] = xb[r].x; sX[k4 + 1][row] = xb[r].y;
            sX[k4 + 2][row] = xb[r].z; sX[k4 + 3][row] = xb[r].w;
            sW[k4 + 0][row] = wb[r].x; sW[k4 + 1][row] = wb[r].y;
            sW[k4 + 2][row] = wb[r].z; sW[k4 + 3][row] = wb[r].w;
            sM[k4 + 0][row] = mb[r].x; sM[k4 + 1][row] = mb[r].y;
            sM[k4 + 2][row] = mb[r].z; sM[k4 + 3][row] = mb[r].w;
        }
        __syncthreads();

        if (k0 + BK < IN) {
            #pragma unroll
            for (int r = 0; r < 2; r++) {
                int idx = tid + r * 128;
                int row = idx >> 2, k4 = (idx & 3) << 2;
                size_t off = (size_t)row * IN + (k0 + BK) + k4;
                xb[r] = *(const float4*)(Xb + off);
                wb[r] = *(const float4*)(Wb + off);
                mb[r] = *(const float4*)(Mb + off);
            }
        }

        #pragma unroll
        for (int kk = 0; kk < BK; kk++) {
            u64 a[4];
            #pragma unroll
            for (int i = 0; i < 4; i++)
                a[i] = *(const u64*)&sX[kk][ty * 8 + 2 * i];
            #pragma unroll
            for (int j = 0; j < 4; j++) {
                u64 w2 = pack2(sW[kk][tx * 4 + j]);
                u64 m2 = pack2(sM[kk][tx * 4 + j]);
                #pragma unroll
                for (int i = 0; i < 4; i++) {
                    accW[j][i] = fma2(a[i], w2, accW[j][i]);
                    accM[j][i] = fma2(a[i], m2, accM[j][i]);
                }
            }
        }
        __syncthreads();
    }

    float bv[4];
    #pragma unroll
    for (int j = 0; j < 4; j++) bv[j] = bg[n_blk + tx * 4 + j];

    float* P = g_P[g];
    #pragma unroll
    for (int i = 0; i < 4; i++) {
        float2 w[4], mm[4];
        #pragma unroll
        for (int j = 0; j < 4; j++) { w[j] = unpack2(accW[j][i]); mm[j] = unpack2(accM[j][i]); }
        const int m = m_blk + ty * 8 + 2 * i;
        float4 v0, v1;
        v0.x = sigmoidf_(mm[0].x) * w[0].x + bv[0];
        v0.y = sigmoidf_(mm[1].x) * w[1].x + bv[1];
        v0.z = sigmoidf_(mm[2].x) * w[2].x + bv[2];
        v0.w = sigmoidf_(mm[3].x) * w[3].x + bv[3];
        v1.x = sigmoidf_(mm[0].y) * w[0].y + bv[0];
        v1.y = sigmoidf_(mm[1].y) * w[1].y + bv[1];
        v1.z = sigmoidf_(mm[2].y) * w[2].y + bv[2];
        v1.w = sigmoidf_(mm[3].y) * w[3].y + bv[3];
        *(float4*)&P[(size_t)m * H + n_blk + tx * 4]       = v0;
        *(float4*)&P[(size_t)(m + 1) * H + n_blk + tx * 4] = v1;
    }
}

// ---------------------------------------------------------------------------
// Persistent recurrence kernel (v3): 512 threads for latency hiding.
// Thread map: tx = tid&7 (n), tb = (tid>>3)&15 (4 b-rows each, b0=tb*4),
// kz = tid>>7 (k-split 4, 256 k each).
// Per thread: 12 u64 accs = 4 b x 3 (U,Um)-pairs. 6 U matrices in SMEM.
// h ping-pong K-MAJOR [n][b]; staged per 32-k round into sH.
// ---------------------------------------------------------------------------
constexpr int SU_WORDS = 1024 * 48;         // [k][n8][mat6]
constexpr int SH_WORDS = 4 * 32 * 64;       // [kz][kk32][b64] = 8192 words (32KB)
constexpr int RSMEM_BYTES = (SU_WORDS + SH_WORDS) * 4;   // 229376 B

__global__ __launch_bounds__(RTHREADS, 1)
void lstm_persist(const float* __restrict__ Uf, const float* __restrict__ Umf,
                  const float* __restrict__ Uo, const float* __restrict__ Umo,
                  const float* __restrict__ Uc, const float* __restrict__ Umc,
                  float* __restrict__ out)
{
    extern __shared__ float smem[];
    float* sU = smem;                 // idx = k*48 + n*6 + mat  (f,mf,o,mo,c,mc)
    float* sH = smem + SU_WORDS;      // idx = (kz*32 + kk)*64 + b

    const int tid = threadIdx.x;
    const int tx  = tid & 7;           // n within slice
    const int tb  = (tid >> 3) & 15;   // b-group (4 rows)
    const int kz  = tid >> 7;          // k partition 0..3
    const int b0  = tb * 4;
    const int nb  = blockIdx.x * 8;
    const int n   = nb + tx;

    // ---- one-time: load U slice into SMEM ----
    {
        const float* Us[6] = {Uf, Umf, Uo, Umo, Uc, Umc};
        for (int i = tid; i < 6 * 8 * 256; i += RTHREADS) {
            int mat  = i >> 11;          // / 2048
            int rest = i & 2047;
            int nn   = rest >> 8;        // / 256
            int q    = (rest & 255) * 4; // k offset
            float4 v = *(const float4*)(Us[mat] + (size_t)(nb + nn) * H + q);
            float* dst = sU + (size_t)q * 48 + nn * 6 + mat;
            dst[0]   = v.x;
            dst[48]  = v.y;
            dst[96]  = v.z;
            dst[144] = v.w;
        }
    }

    // ---- zero h0 slice ([n][b] layout, this block's 8 n-rows): 512 elems ----
    g_h[0][(size_t)(nb + (tid >> 6)) * B + (tid & 63)] = 0.0f;

    float creg[4], hlast[4];
    #pragma unroll
    for (int j = 0; j < 4; j++) { creg[j] = 0.0f; hlast[j] = 0.0f; }

    grid_barrier();   // h0 + all U slices staged

    for (int t = 0; t < T; t++) {
        const float* __restrict__ hp = g_h[t & 1];
        float* __restrict__ hn = g_h[(t + 1) & 1];

        u64 acc[4][3];
        #pragma unroll
        for (int j = 0; j < 4; j++)
            #pragma unroll
            for (int mp = 0; mp < 3; mp++) acc[j][mp] = 0ull;

        // prefetch round 0 (32 k per partition, 32KB chunk, 4 float4/thread)
        float4 pf[4];
        #pragma unroll
        for (int j = 0; j < 4; j++) {
            int fid = tid + j * RTHREADS;
            int row = fid >> 4;               // 0..511? no: 2048 float4/16 = 128 rows
            int b4  = (fid & 15) * 4;
            int kzl = row >> 5, kkl = row & 31;
            pf[j] = ldcg4(hp + (size_t)(kzl * 256 + kkl) * B + b4);
        }

        for (int r = 0; r < 8; r++) {
            __syncthreads();
            #pragma unroll
            for (int j = 0; j < 4; j++) {
                int fid = tid + j * RTHREADS;
                int row = fid >> 4;
                int b4  = (fid & 15) * 4;
                *(float4*)(sH + (size_t)row * 64 + b4) = pf[j];
            }
            __syncthreads();

            if (r < 7) {
                #pragma unroll
                for (int j = 0; j < 4; j++) {
                    int fid = tid + j * RTHREADS;
                    int row = fid >> 4;
                    int b4  = (fid & 15) * 4;
                    int kzl = row >> 5, kkl = row & 31;
                    pf[j] = ldcg4(hp + (size_t)(kzl * 256 + (r + 1) * 32 + kkl) * B + b4);
                }
            }

            const float* wrow = sU + (size_t)(kz * 256 + r * 32) * 48 + tx * 6;
            const float* hrow = sH + (size_t)kz * 32 * 64 + b0;
            #pragma unroll 8
            for (int kk = 0; kk < 32; kk++) {
                u64 w0 = *(const u64*)(wrow + 0);
                u64 w1 = *(const u64*)(wrow + 2);
                u64 w2 = *(const u64*)(wrow + 4);
                float4 ha = *(const float4*)(hrow);
                u64 a0 = pack2(ha.x), a1 = pack2(ha.y), a2 = pack2(ha.z), a3 = pack2(ha.w);
                acc[0][0] = fma2(a0, w0, acc[0][0]); acc[0][1] = fma2(a0, w1, acc[0][1]); acc[0][2] = fma2(a0, w2, acc[0][2]);
                acc[1][0] = fma2(a1, w0, acc[1][0]); acc[1][1] = fma2(a1, w1, acc[1][1]); acc[1][2] = fma2(a1, w2, acc[1][2]);
                acc[2][0] = fma2(a2, w0, acc[2][0]); acc[2][1] = fma2(a2, w1, acc[2][1]); acc[2][2] = fma2(a2, w2, acc[2][2]);
                acc[3][0] = fma2(a3, w0, acc[3][0]); acc[3][1] = fma2(a3, w1, acc[3][1]); acc[3][2] = fma2(a3, w2, acc[3][2]);
                wrow += 48;
                hrow += 64;
            }
        }

        // ---- prefetch g_P for the epilogue (kz==0 only) ----
        float pfP[3][4];
        if (kz == 0) {
            #pragma unroll
            for (int j = 0; j < 4; j++) {
                size_t pidx = ((size_t)((b0 + j) * T + t)) * H + n;
                pfP[0][j] = __ldcs(&g_P[0][pidx]);
                pfP[1][j] = __ldcs(&g_P[1][pidx]);
                pfP[2][j] = __ldcs(&g_P[2][pidx]);
            }
        }

        // ---- k-split reduction (sH reused; cell = (tb,tx), 128 cells/kz) ----
        float2* rbuf = (float2*)sH;          // capacity 4096 float2; use 2*1536
        const int cell = tid & 127;
        __syncthreads();
        if (kz == 1 || kz == 3) {
            float2* dst = rbuf + (kz >> 1) * 1536;
            #pragma unroll
            for (int j = 0; j < 4; j++)
                #pragma unroll
                for (int mp = 0; mp < 3; mp++)
                    dst[(j * 3 + mp) * 128 + cell] = unpack2(acc[j][mp]);
        }
        __syncthreads();
        if (kz == 0 || kz == 2) {
            const float2* src = rbuf + (kz >> 1) * 1536;
            #pragma unroll
            for (int j = 0; j < 4; j++)
                #pragma unroll
                for (int mp = 0; mp < 3; mp++) {
                    float2 s = src[(j * 3 + mp) * 128 + cell];
                    float2 v = unpack2(acc[j][mp]);
                    acc[j][mp] = pack_pair(v.x + s.x, v.y + s.y);
                }
        }
        __syncthreads();
        if (kz == 2) {
            #pragma unroll
            for (int j = 0; j < 4; j++)
                #pragma unroll
                for (int mp = 0; mp < 3; mp++)
                    rbuf[(j * 3 + mp) * 128 + cell] = unpack2(acc[j][mp]);
        }
        __syncthreads();

        // ---- fused LSTM cell epilogue (kz==0 threads own the cells) ----
        if (kz == 0) {
            #pragma unroll
            for (int j = 0; j < 4; j++) {
                int bb = b0 + j;
                float2 vf = unpack2(acc[j][0]);
                float2 vo = unpack2(acc[j][1]);
                float2 vc = unpack2(acc[j][2]);
                float2 sf = rbuf[(j * 3 + 0) * 128 + cell];
                float2 so = rbuf[(j * 3 + 1) * 128 + cell];
                float2 sc = rbuf[(j * 3 + 2) * 128 + cell];
                vf.x += sf.x; vf.y += sf.y;
                vo.x += so.x; vo.y += so.y;
                vc.x += sc.x; vc.y += sc.y;
                float rf = sigmoidf_(vf.y) * vf.x;
                float ro = sigmoidf_(vo.y) * vo.x;
                float rc = sigmoidf_(vc.y) * vc.x;
                float f = sigmoidf_(pfP[0][j] + rf);
                float o = sigmoidf_(pfP[1][j] + ro);
                float cn = f * creg[j] + tanhf(pfP[2][j] + rc);
                creg[j] = cn;
                float hval = o * cn;
                hlast[j] = hval;
                hn[(size_t)n * B + bb] = hval;                       // K-major h
                out[((size_t)(bb * T + t)) * H + n] = hval;
            }
        }

        grid_barrier();
    }

    // final states: h then c, each [B,H], appended after [B,T,H]
    if (kz == 0) {
        #pragma unroll
        for (int j = 0; j < 4; j++) {
            int bb = b0 + j;
            out[(size_t)M * H + (size_t)bb * H + n]                 = hlast[j];
            out[(size_t)M * H + (size_t)B * H + (size_t)bb * H + n] = creg[j];
        }
    }
}

} // anonymous namespace

extern "C" void kernel_launch(void* const* d_in, const int* in_sizes, int n_in,
                              void* d_out, int out_size) {
    (void)in_sizes; (void)n_in; (void)out_size;
    const float* X    = (const float*)d_in[0];
    const float* W_f  = (const float*)d_in[1];
    const float* Wm_f = (const float*)d_in[2];
    const float* U_f  = (const float*)d_in[3];
    const float* Um_f = (const float*)d_in[4];
    const float* b_f  = (const float*)d_in[5];
    // inputs 6..10 (i-gate) are computed but unused by the reference -> skipped
    const float* W_o  = (const float*)d_in[11];
    const float* Wm_o = (const float*)d_in[12];
    const float* U_o  = (const float*)d_in[13];
    const float* Um_o = (const float*)d_in[14];
    const float* b_o  = (const float*)d_in[15];
    const float* W_c  = (const float*)d_in[16];
    const float* Wm_c = (const float*)d_in[17];
    const float* U_c  = (const float*)d_in[18];
    const float* Um_c = (const float*)d_in[19];
    const float* b_c  = (const float*)d_in[20];
    float* out = (float*)d_out;

    static int smem_set = 0;
    if (!smem_set) {
        cudaFuncSetAttribute(lstm_persist,
                             cudaFuncAttributeMaxDynamicSharedMemorySize,
                             RSMEM_BYTES);
        smem_set = 1;
    }

    dim3 pg(H / BN, M / BM, 3);
    input_proj<<<pg, 128>>>(X, W_f, Wm_f, b_f, W_o, Wm_o, b_o, W_c, Wm_c, b_c);

    lstm_persist<<<RGRID, RTHREADS, RSMEM_BYTES>>>(U_f, Um_f, U_o, Um_o, U_c, Um_c, out);
}

// round 9
// speedup vs baseline: 1.0007x; 1.0007x over previous
#include <cuda_runtime.h>
#include <math.h>

namespace {

constexpr int B  = 64;
constexpr int T  = 256;
constexpr int IN = 512;
constexpr int H  = 1024;
constexpr int M  = B * T;   // 16384

constexpr int RGRID = 128;     // persistent blocks, each owns 8 N-columns
constexpr int RTHREADS = 512;  // 16 warps: tx(8) x tb(16) x kz(4)

typedef unsigned long long u64;

// Scratch (device globals — no allocation allowed)
__device__ float g_P[3][(size_t)M * H];   // masked input projections + bias: [f, o, c]
__device__ float g_h[2][H * B];           // h ping-pong, K-MAJOR: [n(H)][b(B)]

// grid barrier state
__device__ unsigned g_bar_count = 0;
__device__ volatile unsigned g_bar_gen = 0;

__device__ __forceinline__ u64 pack2(float v) {
    u64 r; asm("mov.b64 %0, {%1, %2};" : "=l"(r) : "f"(v), "f"(v)); return r;
}
__device__ __forceinline__ u64 pack_pair(float x, float y) {
    u64 r; asm("mov.b64 %0, {%1, %2};" : "=l"(r) : "f"(x), "f"(y)); return r;
}
__device__ __forceinline__ u64 fma2(u64 a, u64 b, u64 c) {
    u64 d; asm("fma.rn.f32x2 %0, %1, %2, %3;" : "=l"(d) : "l"(a), "l"(b), "l"(c)); return d;
}
__device__ __forceinline__ float2 unpack2(u64 v) {
    float2 f; asm("mov.b64 {%0, %1}, %2;" : "=f"(f.x), "=f"(f.y) : "l"(v)); return f;
}
__device__ __forceinline__ float sigmoidf_(float x) { return 1.0f / (1.0f + expf(-x)); }

__device__ __forceinline__ float4 ldcg4(const float* p) {
    float4 v;
    asm volatile("ld.global.cg.v4.f32 {%0,%1,%2,%3}, [%4];"
                 : "=f"(v.x), "=f"(v.y), "=f"(v.z), "=f"(v.w) : "l"(p));
    return v;
}

// All blocks are co-resident (1 block/SM via smem footprint, grid 128 <= 148 SMs).
__device__ __forceinline__ void grid_barrier() {
    __syncthreads();
    if (threadIdx.x == 0) {
        __threadfence();
        unsigned old = g_bar_gen;
        if (atomicAdd(&g_bar_count, 1u) == (unsigned)(gridDim.x - 1)) {
            g_bar_count = 0;
            __threadfence();
            g_bar_gen = old + 1;
        } else {
            while (g_bar_gen == old) { }
        }
        __threadfence();
    }
    __syncthreads();
}

// ---------------------------------------------------------------------------
// Input projection: P_g[m][n] = sigmoid(X[m]·Wm_g[n]) * (X[m]·W_g[n]) + b_g[n]
// GEMM M=16384, N=1024, K=512, two B-matrices per output. (unchanged)
// ---------------------------------------------------------------------------
constexpr int BM = 64, BN = 64, BK = 16;

__global__ __launch_bounds__(128)
void input_proj(const float* __restrict__ X,
                const float* __restrict__ W0, const float* __restrict__ Wm0, const float* __restrict__ b0,
                const float* __restrict__ W1, const float* __restrict__ Wm1, const float* __restrict__ b1,
                const float* __restrict__ W2, const float* __restrict__ Wm2, const float* __restrict__ b2)
{
    __shared__ __align__(16) float sX[BK][BM + 2];
    __shared__ __align__(16) float sW[BK][BN + 2];
    __shared__ __align__(16) float sM[BK][BN + 2];

    const int g = blockIdx.z;
    const float* Wg  = (g == 0) ? W0  : (g == 1) ? W1  : W2;
    const float* Wmg = (g == 0) ? Wm0 : (g == 1) ? Wm1 : Wm2;
    const float* bg  = (g == 0) ? b0  : (g == 1) ? b1  : b2;

    const int tid = threadIdx.x;
    const int tx = tid & 15;
    const int ty = tid >> 4;
    const int m_blk = blockIdx.y * BM;
    const int n_blk = blockIdx.x * BN;

    const float* Xb = X   + (size_t)m_blk * IN;
    const float* Wb = Wg  + (size_t)n_blk * IN;
    const float* Mb = Wmg + (size_t)n_blk * IN;

    u64 accW[4][4], accM[4][4];
    #pragma unroll
    for (int j = 0; j < 4; j++)
        #pragma unroll
        for (int i = 0; i < 4; i++) { accW[j][i] = 0ull; accM[j][i] = 0ull; }

    float4 xb[2], wb[2], mb[2];
    #pragma unroll
    for (int r = 0; r < 2; r++) {
        int idx = tid + r * 128;
        int row = idx >> 2, k4 = (idx & 3) << 2;
        size_t off = (size_t)row * IN + k4;
        xb[r] = *(const float4*)(Xb + off);
        wb[r] = *(const float4*)(Wb + off);
        mb[r] = *(const float4*)(Mb + off);
    }

    for (int k0 = 0; k0 < IN; k0 += BK) {
        #pragma unroll
        for (int r = 0; r < 2; r++) {
            int idx = tid + r * 128;
            int row = idx >> 2, k4 = (idx & 3) << 2;
            sX[k4 + 0][row] = xb[r].x; sX[k4 + 1][row] = xb[r].y;
            sX[k4 + 2][row] = xb[r].z; sX[k4 + 3][row] = xb[r].w;
            sW[k4 + 0][row] = wb[r].x; sW[k4 + 1][row] = wb[r].y;
            sW[k4 + 2][row] = wb[r].z; sW[k4 + 3][row] = wb[r].w;
            sM[k4 + 0][row] = mb[r].x; sM[k4 + 1][row] = mb[r].y;
            sM[k4 + 2][row] = mb[r].z; sM[k4 + 3][row] = mb[r].w;
        }
        __syncthreads();

        if (k0 + BK < IN) {
            #pragma unroll
            for (int r = 0; r < 2; r++) {
                int idx = tid + r * 128;
                int row = idx >> 2, k4 = (idx & 3) << 2;
                size_t off = (size_t)row * IN + (k0 + BK) + k4;
                xb[r] = *(const float4*)(Xb + off);
                wb[r] = *(const float4*)(Wb + off);
                mb[r] = *(const float4*)(Mb + off);
            }
        }

        #pragma unroll
        for (int kk = 0; kk < BK; kk++) {
            u64 a[4];
            #pragma unroll
            for (int i = 0; i < 4; i++)
                a[i] = *(const u64*)&sX[kk][ty * 8 + 2 * i];
            #pragma unroll
            for (int j = 0; j < 4; j++) {
                u64 w2 = pack2(sW[kk][tx * 4 + j]);
                u64 m2 = pack2(sM[kk][tx * 4 + j]);
                #pragma unroll
                for (int i = 0; i < 4; i++) {
                    accW[j][i] = fma2(a[i], w2, accW[j][i]);
                    accM[j][i] = fma2(a[i], m2, accM[j][i]);
                }
            }
        }
        __syncthreads();
    }

    float bv[4];
    #pragma unroll
    for (int j = 0; j < 4; j++) bv[j] = bg[n_blk + tx * 4 + j];

    float* P = g_P[g];
    #pragma unroll
    for (int i = 0; i < 4; i++) {
        float2 w[4], mm[4];
        #pragma unroll
        for (int j = 0; j < 4; j++) { w[j] = unpack2(accW[j][i]); mm[j] = unpack2(accM[j][i]); }
        const int m = m_blk + ty * 8 + 2 * i;
        float4 v0, v1;
        v0.x = sigmoidf_(mm[0].x) * w[0].x + bv[0];
        v0.y = sigmoidf_(mm[1].x) * w[1].x + bv[1];
        v0.z = sigmoidf_(mm[2].x) * w[2].x + bv[2];
        v0.w = sigmoidf_(mm[3].x) * w[3].x + bv[3];
        v1.x = sigmoidf_(mm[0].y) * w[0].y + bv[0];
        v1.y = sigmoidf_(mm[1].y) * w[1].y + bv[1];
        v1.z = sigmoidf_(mm[2].y) * w[2].y + bv[2];
        v1.w = sigmoidf_(mm[3].y) * w[3].y + bv[3];
        *(float4*)&P[(size_t)m * H + n_blk + tx * 4]       = v0;
        *(float4*)&P[(size_t)(m + 1) * H + n_blk + tx * 4] = v1;
    }
}

// ---------------------------------------------------------------------------
// Persistent recurrence kernel (v3): 512 threads for latency hiding.
// Thread map: tx = tid&7 (n), tb = (tid>>3)&15 (4 b-rows each, b0=tb*4),
// kz = tid>>7 (k-split 4, 256 k each).
// Per thread: 12 u64 accs = 4 b x 3 (U,Um)-pairs. 6 U matrices in SMEM.
// h ping-pong K-MAJOR [n][b]; staged per 32-k round into sH.
// ---------------------------------------------------------------------------
constexpr int SU_WORDS = 1024 * 48;         // [k][n8][mat6]
constexpr int SH_WORDS = 4 * 32 * 64;       // [kz][kk32][b64] = 8192 words (32KB)
constexpr int RSMEM_BYTES = (SU_WORDS + SH_WORDS) * 4;   // 229376 B

__global__ __launch_bounds__(RTHREADS, 1)
void lstm_persist(const float* __restrict__ Uf, const float* __restrict__ Umf,
                  const float* __restrict__ Uo, const float* __restrict__ Umo,
                  const float* __restrict__ Uc, const float* __restrict__ Umc,
                  float* __restrict__ out)
{
    extern __shared__ float smem[];
    float* sU = smem;                 // idx = k*48 + n*6 + mat  (f,mf,o,mo,c,mc)
    float* sH = smem + SU_WORDS;      // idx = (kz*32 + kk)*64 + b

    const int tid = threadIdx.x;
    const int tx  = tid & 7;           // n within slice
    const int tb  = (tid >> 3) & 15;   // b-group (4 rows)
    const int kz  = tid >> 7;          // k partition 0..3
    const int b0  = tb * 4;
    const int nb  = blockIdx.x * 8;
    const int n   = nb + tx;

    // ---- one-time: load U slice into SMEM ----
    {
        const float* Us[6] = {Uf, Umf, Uo, Umo, Uc, Umc};
        for (int i = tid; i < 6 * 8 * 256; i += RTHREADS) {
            int mat  = i >> 11;          // / 2048
            int rest = i & 2047;
            int nn   = rest >> 8;        // / 256
            int q    = (rest & 255) * 4; // k offset
            float4 v = *(const float4*)(Us[mat] + (size_t)(nb + nn) * H + q);
            float* dst = sU + (size_t)q * 48 + nn * 6 + mat;
            dst[0]   = v.x;
            dst[48]  = v.y;
            dst[96]  = v.z;
            dst[144] = v.w;
        }
    }

    // ---- zero h0 slice ([n][b] layout, this block's 8 n-rows): 512 elems ----
    g_h[0][(size_t)(nb + (tid >> 6)) * B + (tid & 63)] = 0.0f;

    float creg[4], hlast[4];
    #pragma unroll
    for (int j = 0; j < 4; j++) { creg[j] = 0.0f; hlast[j] = 0.0f; }

    grid_barrier();   // h0 + all U slices staged

    for (int t = 0; t < T; t++) {
        const float* __restrict__ hp = g_h[t & 1];
        float* __restrict__ hn = g_h[(t + 1) & 1];

        u64 acc[4][3];
        #pragma unroll
        for (int j = 0; j < 4; j++)
            #pragma unroll
            for (int mp = 0; mp < 3; mp++) acc[j][mp] = 0ull;

        // prefetch round 0 (32 k per partition, 32KB chunk, 4 float4/thread)
        float4 pf[4];
        #pragma unroll
        for (int j = 0; j < 4; j++) {
            int fid = tid + j * RTHREADS;
            int row = fid >> 4;               // 0..511? no: 2048 float4/16 = 128 rows
            int b4  = (fid & 15) * 4;
            int kzl = row >> 5, kkl = row & 31;
            pf[j] = ldcg4(hp + (size_t)(kzl * 256 + kkl) * B + b4);
        }

        for (int r = 0; r < 8; r++) {
            __syncthreads();
            #pragma unroll
            for (int j = 0; j < 4; j++) {
                int fid = tid + j * RTHREADS;
                int row = fid >> 4;
                int b4  = (fid & 15) * 4;
                *(float4*)(sH + (size_t)row * 64 + b4) = pf[j];
            }
            __syncthreads();

            if (r < 7) {
                #pragma unroll
                for (int j = 0; j < 4; j++) {
                    int fid = tid + j * RTHREADS;
                    int row = fid >> 4;
                    int b4  = (fid & 15) * 4;
                    int kzl = row >> 5, kkl = row & 31;
                    pf[j] = ldcg4(hp + (size_t)(kzl * 256 + (r + 1) * 32 + kkl) * B + b4);
                }
            }

            const float* wrow = sU + (size_t)(kz * 256 + r * 32) * 48 + tx * 6;
            const float* hrow = sH + (size_t)kz * 32 * 64 + b0;
            #pragma unroll 8
            for (int kk = 0; kk < 32; kk++) {
                u64 w0 = *(const u64*)(wrow + 0);
                u64 w1 = *(const u64*)(wrow + 2);
                u64 w2 = *(const u64*)(wrow + 4);
                float4 ha = *(const float4*)(hrow);
                u64 a0 = pack2(ha.x), a1 = pack2(ha.y), a2 = pack2(ha.z), a3 = pack2(ha.w);
                acc[0][0] = fma2(a0, w0, acc[0][0]); acc[0][1] = fma2(a0, w1, acc[0][1]); acc[0][2] = fma2(a0, w2, acc[0][2]);
                acc[1][0] = fma2(a1, w0, acc[1][0]); acc[1][1] = fma2(a1, w1, acc[1][1]); acc[1][2] = fma2(a1, w2, acc[1][2]);
                acc[2][0] = fma2(a2, w0, acc[2][0]); acc[2][1] = fma2(a2, w1, acc[2][1]); acc[2][2] = fma2(a2, w2, acc[2][2]);
                acc[3][0] = fma2(a3, w0, acc[3][0]); acc[3][1] = fma2(a3, w1, acc[3][1]); acc[3][2] = fma2(a3, w2, acc[3][2]);
                wrow += 48;
                hrow += 64;
            }
        }

        // ---- prefetch g_P for the epilogue (kz==0 only) ----
        float pfP[3][4];
        if (kz == 0) {
            #pragma unroll
            for (int j = 0; j < 4; j++) {
                size_t pidx = ((size_t)((b0 + j) * T + t)) * H + n;
                pfP[0][j] = __ldcs(&g_P[0][pidx]);
                pfP[1][j] = __ldcs(&g_P[1][pidx]);
                pfP[2][j] = __ldcs(&g_P[2][pidx]);
            }
        }

        // ---- k-split reduction (sH reused; cell = (tb,tx), 128 cells/kz) ----
        float2* rbuf = (float2*)sH;          // capacity 4096 float2; use 2*1536
        const int cell = tid & 127;
        __syncthreads();
        if (kz == 1 || kz == 3) {
            float2* dst = rbuf + (kz >> 1) * 1536;
            #pragma unroll
            for (int j = 0; j < 4; j++)
                #pragma unroll
                for (int mp = 0; mp < 3; mp++)
                    dst[(j * 3 + mp) * 128 + cell] = unpack2(acc[j][mp]);
        }
        __syncthreads();
        if (kz == 0 || kz == 2) {
            const float2* src = rbuf + (kz >> 1) * 1536;
            #pragma unroll
            for (int j = 0; j < 4; j++)
                #pragma unroll
                for (int mp = 0; mp < 3; mp++) {
                    float2 s = src[(j * 3 + mp) * 128 + cell];
                    float2 v = unpack2(acc[j][mp]);
                    acc[j][mp] = pack_pair(v.x + s.x, v.y + s.y);
                }
        }
        __syncthreads();
        if (kz == 2) {
            #pragma unroll
            for (int j = 0; j < 4; j++)
                #pragma unroll
                for (int mp = 0; mp < 3; mp++)
                    rbuf[(j * 3 + mp) * 128 + cell] = unpack2(acc[j][mp]);
        }
        __syncthreads();

        // ---- fused LSTM cell epilogue (kz==0 threads own the cells) ----
        if (kz == 0) {
            #pragma unroll
            for (int j = 0; j < 4; j++) {
                int bb = b0 + j;
                float2 vf = unpack2(acc[j][0]);
                float2 vo = unpack2(acc[j][1]);
                float2 vc = unpack2(acc[j][2]);
                float2 sf = rbuf[(j * 3 + 0) * 128 + cell];
                float2 so = rbuf[(j * 3 + 1) * 128 + cell];
                float2 sc = rbuf[(j * 3 + 2) * 128 + cell];
                vf.x += sf.x; vf.y += sf.y;
                vo.x += so.x; vo.y += so.y;
                vc.x += sc.x; vc.y += sc.y;
                float rf = sigmoidf_(vf.y) * vf.x;
                float ro = sigmoidf_(vo.y) * vo.x;
                float rc = sigmoidf_(vc.y) * vc.x;
                float f = sigmoidf_(pfP[0][j] + rf);
                float o = sigmoidf_(pfP[1][j] + ro);
                float cn = f * creg[j] + tanhf(pfP[2][j] + rc);
                creg[j] = cn;
                float hval = o * cn;
                hlast[j] = hval;
                hn[(size_t)n * B + bb] = hval;                       // K-major h
                out[((size_t)(bb * T + t)) * H + n] = hval;
            }
        }

        grid_barrier();
    }

    // final states: h then c, each [B,H], appended after [B,T,H]
    if (kz == 0) {
        #pragma unroll
        for (int j = 0; j < 4; j++) {
            int bb = b0 + j;
            out[(size_t)M * H + (size_t)bb * H + n]                 = hlast[j];
            out[(size_t)M * H + (size_t)B * H + (size_t)bb * H + n] = creg[j];
        }
    }
}

} // anonymous namespace

extern "C" void kernel_launch(void* const* d_in, const int* in_sizes, int n_in,
                              void* d_out, int out_size) {
    (void)in_sizes; (void)n_in; (void)out_size;
    const float* X    = (const float*)d_in[0];
    const float* W_f  = (const float*)d_in[1];
    const float* Wm_f = (const float*)d_in[2];
    const float* U_f  = (const float*)d_in[3];
    const float* Um_f = (const float*)d_in[4];
    const float* b_f  = (const float*)d_in[5];
    // inputs 6..10 (i-gate) are computed but unused by the reference -> skipped
    const float* W_o  = (const float*)d_in[11];
    const float* Wm_o = (const float*)d_in[12];
    const float* U_o  = (const float*)d_in[13];
    const float* Um_o = (const float*)d_in[14];
    const float* b_o  = (const float*)d_in[15];
    const float* W_c  = (const float*)d_in[16];
    const float* Wm_c = (const float*)d_in[17];
    const float* U_c  = (const float*)d_in[18];
    const float* Um_c = (const float*)d_in[19];
    const float* b_c  = (const float*)d_in[20];
    float* out = (float*)d_out;

    static int smem_set = 0;
    if (!smem_set) {
        cudaFuncSetAttribute(lstm_persist,
                             cudaFuncAttributeMaxDynamicSharedMemorySize,
                             RSMEM_BYTES);
        smem_set = 1;
    }

    dim3 pg(H / BN, M / BM, 3);
    input_proj<<<pg, 128>>>(X, W_f, Wm_f, b_f, W_o, Wm_o, b_o, W_c, Wm_c, b_c);

    lstm_persist<<<RGRID, RTHREADS, RSMEM_BYTES>>>(U_f, Um_f, U_o, Um_o, U_c, Um_c, out);
}

// round 12
// speedup vs baseline: 1.2158x; 1.2149x over previous
#include <cuda_runtime.h>
#include <cuda_bf16.h>
#include <cstdint>
#include <math.h>

namespace {

constexpr int B  = 64;
constexpr int T  = 256;
constexpr int IN = 512;
constexpr int H  = 1024;
constexpr int M  = B * T;   // 16384

typedef unsigned long long u64;
typedef unsigned int u32;

// ---------------- device scratch (no allocation allowed) ----------------
__device__ float g_P[3][(size_t)M * H];       // input projections + bias: [f, o, c]
__device__ __nv_bfloat16 g_hh[2][B * H];      // h hi bf16, [b][k], ping-pong
__device__ __nv_bfloat16 g_hl[2][B * H];      // h lo bf16

__device__ unsigned g_bar_count = 0;
__device__ volatile unsigned g_bar_gen = 0;

// ---------------- scalar helpers ----------------
__device__ __forceinline__ u64 pack2(float v) {
    u64 r; asm("mov.b64 %0, {%1, %2};" : "=l"(r) : "f"(v), "f"(v)); return r;
}
__device__ __forceinline__ u64 fma2(u64 a, u64 b, u64 c) {
    u64 d; asm("fma.rn.f32x2 %0, %1, %2, %3;" : "=l"(d) : "l"(a), "l"(b), "l"(c)); return d;
}
__device__ __forceinline__ float2 unpack2(u64 v) {
    float2 f; asm("mov.b64 {%0, %1}, %2;" : "=f"(f.x), "=f"(f.y) : "l"(v)); return f;
}
__device__ __forceinline__ float sigmoidf_(float x) { return 1.0f / (1.0f + expf(-x)); }

__device__ __forceinline__ u32 smem_u32(const void* p) {
    u32 a;
    asm("{ .reg .u64 t; cvta.to.shared.u64 t, %1; cvt.u32.u64 %0, t; }" : "=r"(a) : "l"(p));
    return a;
}
__device__ __forceinline__ uint4 ldcg_u4(const void* p) {
    uint4 v;
    asm volatile("ld.global.cg.v4.u32 {%0,%1,%2,%3}, [%4];"
                 : "=r"(v.x), "=r"(v.y), "=r"(v.z), "=r"(v.w) : "l"(p));
    return v;
}

// All blocks co-resident (1 block/SM via smem, grid=128 <= 148 SMs).
__device__ __forceinline__ void grid_barrier() {
    __syncthreads();
    if (threadIdx.x == 0) {
        __threadfence();
        unsigned old = g_bar_gen;
        if (atomicAdd(&g_bar_count, 1u) == (unsigned)(gridDim.x - 1)) {
            g_bar_count = 0;
            __threadfence();
            g_bar_gen = old + 1;
        } else {
            while (g_bar_gen == old) { }
        }
        __threadfence();
    }
    __syncthreads();
}

// ---------------- HMMA helpers (base PTX, sm_80+: works on sm_100) ------
__device__ __forceinline__ void ldsm_x4(u32& r0, u32& r1, u32& r2, u32& r3, u32 addr) {
    asm volatile("ldmatrix.sync.aligned.m8n8.x4.shared.b16 {%0,%1,%2,%3}, [%4];"
                 : "=r"(r0), "=r"(r1), "=r"(r2), "=r"(r3) : "r"(addr));
}
__device__ __forceinline__ void mma16816(float* c, const u32* a, u32 b0, u32 b1) {
    asm volatile(
        "mma.sync.aligned.m16n8k16.row.col.f32.bf16.bf16.f32 "
        "{%0,%1,%2,%3}, {%4,%5,%6,%7}, {%8,%9}, {%0,%1,%2,%3};"
        : "+f"(c[0]), "+f"(c[1]), "+f"(c[2]), "+f"(c[3])
        : "r"(a[0]), "r"(a[1]), "r"(a[2]), "r"(a[3]), "r"(b0), "r"(b1));
}

// ---------------------------------------------------------------------------
// Input projection (unchanged, known-good)
// ---------------------------------------------------------------------------
constexpr int BM = 64, BN = 64, BK = 16;

__global__ __launch_bounds__(128)
void input_proj(const float* __restrict__ X,
                const float* __restrict__ W0, const float* __restrict__ Wm0, const float* __restrict__ b0,
                const float* __restrict__ W1, const float* __restrict__ Wm1, const float* __restrict__ b1,
                const float* __restrict__ W2, const float* __restrict__ Wm2, const float* __restrict__ b2)
{
    __shared__ __align__(16) float sX[BK][BM + 2];
    __shared__ __align__(16) float sW[BK][BN + 2];
    __shared__ __align__(16) float sM[BK][BN + 2];

    const int g = blockIdx.z;
    const float* Wg  = (g == 0) ? W0  : (g == 1) ? W1  : W2;
    const float* Wmg = (g == 0) ? Wm0 : (g == 1) ? Wm1 : Wm2;
    const float* bg  = (g == 0) ? b0  : (g == 1) ? b1  : b2;

    const int tid = threadIdx.x;
    const int tx = tid & 15;
    const int ty = tid >> 4;
    const int m_blk = blockIdx.y * BM;
    const int n_blk = blockIdx.x * BN;

    const float* Xb = X   + (size_t)m_blk * IN;
    const float* Wb = Wg  + (size_t)n_blk * IN;
    const float* Mb = Wmg + (size_t)n_blk * IN;

    u64 accW[4][4], accM[4][4];
    #pragma unroll
    for (int j = 0; j < 4; j++)
        #pragma unroll
        for (int i = 0; i < 4; i++) { accW[j][i] = 0ull; accM[j][i] = 0ull; }

    float4 xb[2], wb[2], mb[2];
    #pragma unroll
    for (int r = 0; r < 2; r++) {
        int idx = tid + r * 128;
        int row = idx >> 2, k4 = (idx & 3) << 2;
        size_t off = (size_t)row * IN + k4;
        xb[r] = *(const float4*)(Xb + off);
        wb[r] = *(const float4*)(Wb + off);
        mb[r] = *(const float4*)(Mb + off);
    }

    for (int k0 = 0; k0 < IN; k0 += BK) {
        #pragma unroll
        for (int r = 0; r < 2; r++) {
            int idx = tid + r * 128;
            int row = idx >> 2, k4 = (idx & 3) << 2;
            sX[k4 + 0][row] = xb[r].x; sX[k4 + 1][row] = xb[r].y;
            sX[k4 + 2][row] = xb[r].z; sX[k4 + 3][row] = xb[r].w;
            sW[k4 + 0][row] = wb[r].x; sW[k4 + 1][row] = wb[r].y;
            sW[k4 + 2][row] = wb[r].z; sW[k4 + 3][row] = wb[r].w;
            sM[k4 + 0][row] = mb[r].x; sM[k4 + 1][row] = mb[r].y;
            sM[k4 + 2][row] = mb[r].z; sM[k4 + 3][row] = mb[r].w;
        }
        __syncthreads();

        if (k0 + BK < IN) {
            #pragma unroll
            for (int r = 0; r < 2; r++) {
                int idx = tid + r * 128;
                int row = idx >> 2, k4 = (idx & 3) << 2;
                size_t off = (size_t)row * IN + (k0 + BK) + k4;
                xb[r] = *(const float4*)(Xb + off);
                wb[r] = *(const float4*)(Wb + off);
                mb[r] = *(const float4*)(Mb + off);
            }
        }

        #pragma unroll
        for (int kk = 0; kk < BK; kk++) {
            u64 a[4];
            #pragma unroll
            for (int i = 0; i < 4; i++)
                a[i] = *(const u64*)&sX[kk][ty * 8 + 2 * i];
            #pragma unroll
            for (int j = 0; j < 4; j++) {
                u64 w2 = pack2(sW[kk][tx * 4 + j]);
                u64 m2 = pack2(sM[kk][tx * 4 + j]);
                #pragma unroll
                for (int i = 0; i < 4; i++) {
                    accW[j][i] = fma2(a[i], w2, accW[j][i]);
                    accM[j][i] = fma2(a[i], m2, accM[j][i]);
                }
            }
        }
        __syncthreads();
    }

    float bv[4];
    #pragma unroll
    for (int j = 0; j < 4; j++) bv[j] = bg[n_blk + tx * 4 + j];

    float* P = g_P[g];
    #pragma unroll
    for (int i = 0; i < 4; i++) {
        float2 w[4], mm[4];
        #pragma unroll
        for (int j = 0; j < 4; j++) { w[j] = unpack2(accW[j][i]); mm[j] = unpack2(accM[j][i]); }
        const int m = m_blk + ty * 8 + 2 * i;
        float4 v0, v1;
        v0.x = sigmoidf_(mm[0].x) * w[0].x + bv[0];
        v0.y = sigmoidf_(mm[1].x) * w[1].x + bv[1];
        v0.z = sigmoidf_(mm[2].x) * w[2].x + bv[2];
        v0.w = sigmoidf_(mm[3].x) * w[3].x + bv[3];
        v1.x = sigmoidf_(mm[0].y) * w[0].y + bv[0];
        v1.y = sigmoidf_(mm[1].y) * w[1].y + bv[1];
        v1.z = sigmoidf_(mm[2].y) * w[2].y + bv[2];
        v1.w = sigmoidf_(mm[3].y) * w[3].y + bv[3];
        *(float4*)&P[(size_t)m * H + n_blk + tx * 4]       = v0;
        *(float4*)&P[(size_t)(m + 1) * H + n_blk + tx * 4] = v1;
    }
}

// ---------------------------------------------------------------------------
// Persistent HMMA recurrence.
// Block owns 8 n-cols => 48 B-rows (r = j*6 + mat; mats f,mf,o,mo,c,mc).
// SMEM: Uh rows 0-47, Ul rows 48-95 (bf16, row stride 2064B -> conflict-free
// ldmatrix). Per step, 32 chunks of 32-k: A [128 rows x 32k] bf16 (rows 0-63
// = hh[b], 64-127 = hl[b]), double buffered.
// Warp w computes A rows 32w..32w+31. Warps 0,1 (hh): x (Uh,Ul) 12 n8-tiles;
// warps 2,3 (hl): x Uh only. R = hh*Uh + hh*Ul + hl*Uh (hl*Ul ~2^-18, dropped).
// ---------------------------------------------------------------------------
constexpr int BROWS   = 2064;              // B row stride bytes (1024*2 + 16 pad)
constexpr int SM_B    = 0;                 // 96 * 2064 = 198144
constexpr int SM_A0   = 198144;            // 128 * 80
constexpr int SM_A1   = 208384;
constexpr int AROWS   = 80;                // 32*2 + 16 pad
constexpr int SM_RED  = 198144;            // overlaps A bufs; f32 [2][64][48] = 24576
constexpr int LSMEM   = 222720;

__global__ __launch_bounds__(128, 1)
void lstm_mma(const float* __restrict__ Uf, const float* __restrict__ Umf,
              const float* __restrict__ Uo, const float* __restrict__ Umo,
              const float* __restrict__ Uc, const float* __restrict__ Umc,
              float* __restrict__ out)
{
    extern __shared__ char dyn[];
    const u32 sb = smem_u32(dyn);
    const int tid = threadIdx.x, wid = tid >> 5, lane = tid & 31;
    const int nb = blockIdx.x * 8;

    // ---- one-time: U -> bf16 hi/lo rows in SMEM ----
    {
        const float* Us[6] = {Uf, Umf, Uo, Umo, Uc, Umc};
        for (int idx = tid; idx < 48 * 256; idx += 128) {
            int r = idx >> 8, q = idx & 255;
            int j = r / 6, mat = r - j * 6;
            float4 v = *(const float4*)(Us[mat] + (size_t)(nb + j) * H + q * 4);
            __nv_bfloat16 h0 = __float2bfloat16(v.x), h1 = __float2bfloat16(v.y);
            __nv_bfloat16 h2 = __float2bfloat16(v.z), h3 = __float2bfloat16(v.w);
            __nv_bfloat16 l0 = __float2bfloat16(v.x - __bfloat162float(h0));
            __nv_bfloat16 l1 = __float2bfloat16(v.y - __bfloat162float(h1));
            __nv_bfloat16 l2 = __float2bfloat16(v.z - __bfloat162float(h2));
            __nv_bfloat16 l3 = __float2bfloat16(v.w - __bfloat162float(h3));
            uint2 uh, ul;
            uh.x = (u32)__bfloat16_as_ushort(h0) | ((u32)__bfloat16_as_ushort(h1) << 16);
            uh.y = (u32)__bfloat16_as_ushort(h2) | ((u32)__bfloat16_as_ushort(h3) << 16);
            ul.x = (u32)__bfloat16_as_ushort(l0) | ((u32)__bfloat16_as_ushort(l1) << 16);
            ul.y = (u32)__bfloat16_as_ushort(l2) | ((u32)__bfloat16_as_ushort(l3) << 16);
            *(uint2*)(dyn + SM_B + r * BROWS + q * 8)          = uh;
            *(uint2*)(dyn + SM_B + (48 + r) * BROWS + q * 8)   = ul;
        }
    }

    // ---- zero h0 (chip-wide split: 16384 u64 per array) ----
    {
        int gi = blockIdx.x * 128 + tid;
        ((u64*)g_hh[0])[gi] = 0ull;
        ((u64*)g_hl[0])[gi] = 0ull;
    }

    float creg[8], hlast[8];
    #pragma unroll
    for (int j = 0; j < 8; j++) { creg[j] = 0.0f; hlast[j] = 0.0f; }

    // loop-invariant ldmatrix offsets
    u32 aoff[2];
    #pragma unroll
    for (int t = 0; t < 2; t++)
        aoff[t] = (u32)((wid * 32 + t * 16 + (lane & 15)) * AROWS + (lane >> 4) * 16);
    u32 boffh[3];
    #pragma unroll
    for (int pp = 0; pp < 3; pp++) {
        int rb = pp * 16 + ((lane >> 4) & 1) * 8 + (lane & 7);
        int kh = ((lane >> 3) & 1) * 16;
        boffh[pp] = sb + SM_B + (u32)(rb * BROWS + kh);
    }
    const u32 bloff = 48u * BROWS;   // Ul rows offset

    // staging map: thread handles flat quads f = tid + 128*j; row = f>>2, q = f&3
    grid_barrier();

    for (int t = 0; t < T; t++) {
        const int par = t & 1;

        // stage chunk 0
        {
            char* A = dyn + SM_A0;
            #pragma unroll
            for (int j = 0; j < 4; j++) {
                int f = tid + 128 * j;
                int row = f >> 2, q = f & 3;
                const __nv_bfloat16* src = (row < 64)
                    ? g_hh[par] + (size_t)row * H + q * 8
                    : g_hl[par] + (size_t)(row - 64) * H + q * 8;
                uint4 v = ldcg_u4(src);
                *(uint4*)(A + row * AROWS + q * 16) = v;
            }
        }
        __syncthreads();

        float acc[2][12][4];
        #pragma unroll
        for (int t2 = 0; t2 < 2; t2++)
            #pragma unroll
            for (int nt = 0; nt < 12; nt++)
                #pragma unroll
                for (int e = 0; e < 4; e++) acc[t2][nt][e] = 0.0f;

        for (int ci = 0; ci < 32; ci++) {
            const int cur = ci & 1;

            // prefetch next chunk into regs
            uint4 nxt[4];
            if (ci < 31) {
                const int k0n = (ci + 1) * 32;
                #pragma unroll
                for (int j = 0; j < 4; j++) {
                    int f = tid + 128 * j;
                    int row = f >> 2, q = f & 3;
                    const __nv_bfloat16* src = (row < 64)
                        ? g_hh[par] + (size_t)row * H + k0n + q * 8
                        : g_hl[par] + (size_t)(row - 64) * H + k0n + q * 8;
                    nxt[j] = ldcg_u4(src);
                }
            }

            // mma on current buffer
            const u32 abase = sb + (cur ? SM_A1 : SM_A0);
            const u32 kbyte = (u32)(ci * 64);   // global k offset in bytes for B
            #pragma unroll
            for (int kk = 0; kk < 2; kk++) {
                u32 a0[4], a1[4];
                ldsm_x4(a0[0], a0[1], a0[2], a0[3], abase + aoff[0] + kk * 32);
                ldsm_x4(a1[0], a1[1], a1[2], a1[3], abase + aoff[1] + kk * 32);
                #pragma unroll
                for (int pp = 0; pp < 3; pp++) {
                    u32 b0, b1, b2, b3;
                    ldsm_x4(b0, b1, b2, b3, boffh[pp] + kbyte + kk * 32);
                    mma16816(acc[0][pp * 2 + 0], a0, b0, b1);
                    mma16816(acc[0][pp * 2 + 1], a0, b2, b3);
                    mma16816(acc[1][pp * 2 + 0], a1, b0, b1);
                    mma16816(acc[1][pp * 2 + 1], a1, b2, b3);
                }
                if (wid < 2) {
                    #pragma unroll
                    for (int pp = 0; pp < 3; pp++) {
                        u32 b0, b1, b2, b3;
                        ldsm_x4(b0, b1, b2, b3, boffh[pp] + bloff + kbyte + kk * 32);
                        mma16816(acc[0][6 + pp * 2 + 0], a0, b0, b1);
                        mma16816(acc[0][6 + pp * 2 + 1], a0, b2, b3);
                        mma16816(acc[1][6 + pp * 2 + 0], a1, b0, b1);
                        mma16816(acc[1][6 + pp * 2 + 1], a1, b2, b3);
                    }
                }
            }

            // store next chunk
            if (ci < 31) {
                char* A = dyn + (cur ? SM_A0 : SM_A1);
                #pragma unroll
                for (int j = 0; j < 4; j++) {
                    int f = tid + 128 * j;
                    int row = f >> 2, q = f & 3;
                    *(uint4*)(A + row * AROWS + q * 16) = nxt[j];
                }
            }
            __syncthreads();
        }

        // prefetch P for epilogue threads (b = tid for tid < 64)
        float Pf[8], Po[8], Pc[8];
        if (tid < 64) {
            size_t base = ((size_t)tid * T + t) * H + nb;
            *(float4*)&Pf[0] = *(const float4*)(g_P[0] + base);
            *(float4*)&Pf[4] = *(const float4*)(g_P[0] + base + 4);
            *(float4*)&Po[0] = *(const float4*)(g_P[1] + base);
            *(float4*)&Po[4] = *(const float4*)(g_P[1] + base + 4);
            *(float4*)&Pc[0] = *(const float4*)(g_P[2] + base);
            *(float4*)&Pc[4] = *(const float4*)(g_P[2] + base + 4);
        }
        __syncthreads();   // A buffers now free for reduction reuse

        // combine Bh+Bl parts in-register (hh warps), write partials
        if (wid < 2) {
            #pragma unroll
            for (int t2 = 0; t2 < 2; t2++)
                #pragma unroll
                for (int nt = 0; nt < 6; nt++)
                    #pragma unroll
                    for (int e = 0; e < 4; e++)
                        acc[t2][nt][e] += acc[t2][nt + 6][e];
        }
        {
            const int half = wid >> 1;            // 0: hh, 1: hl
            const int bbase = (wid & 1) * 32;
            float* red = (float*)(dyn + SM_RED) + half * (64 * 48);
            #pragma unroll
            for (int t2 = 0; t2 < 2; t2++) {
                #pragma unroll
                for (int nt = 0; nt < 6; nt++) {
                    int rrow = bbase + t2 * 16 + (lane >> 2);
                    int col = nt * 8 + (lane & 3) * 2;
                    *(float2*)&red[rrow * 48 + col] =
                        make_float2(acc[t2][nt][0], acc[t2][nt][1]);
                    *(float2*)&red[(rrow + 8) * 48 + col] =
                        make_float2(acc[t2][nt][2], acc[t2][nt][3]);
                }
            }
        }
        __syncthreads();

        // fused LSTM cell epilogue (threads 0..63, b = tid)
        if (tid < 64) {
            const int b = tid;
            const float* r0 = (const float*)(dyn + SM_RED) + b * 48;
            const float* r1 = r0 + 64 * 48;
            float hv[8];
            #pragma unroll
            for (int j = 0; j < 8; j++) {
                float vf  = r0[j * 6 + 0] + r1[j * 6 + 0];
                float vmf = r0[j * 6 + 1] + r1[j * 6 + 1];
                float vo  = r0[j * 6 + 2] + r1[j * 6 + 2];
                float vmo = r0[j * 6 + 3] + r1[j * 6 + 3];
                float vc  = r0[j * 6 + 4] + r1[j * 6 + 4];
                float vmc = r0[j * 6 + 5] + r1[j * 6 + 5];
                float rf = sigmoidf_(vmf) * vf;
                float ro = sigmoidf_(vmo) * vo;
                float rc = sigmoidf_(vmc) * vc;
                float f = sigmoidf_(Pf[j] + rf);
                float o = sigmoidf_(Po[j] + ro);
                float cn = f * creg[j] + tanhf(Pc[j] + rc);
                creg[j] = cn;
                hv[j] = o * cn;
                hlast[j] = hv[j];
            }
            size_t obase = ((size_t)b * T + t) * H + nb;
            *(float4*)(out + obase)     = make_float4(hv[0], hv[1], hv[2], hv[3]);
            *(float4*)(out + obase + 4) = make_float4(hv[4], hv[5], hv[6], hv[7]);

            uint4 uh, ul;
            {
                u32 hw[8], lw[8];
                #pragma unroll
                for (int j = 0; j < 8; j++) {
                    __nv_bfloat16 hb = __float2bfloat16(hv[j]);
                    __nv_bfloat16 lb = __float2bfloat16(hv[j] - __bfloat162float(hb));
                    hw[j] = __bfloat16_as_ushort(hb);
                    lw[j] = __bfloat16_as_ushort(lb);
                }
                uh.x = hw[0] | (hw[1] << 16); uh.y = hw[2] | (hw[3] << 16);
                uh.z = hw[4] | (hw[5] << 16); uh.w = hw[6] | (hw[7] << 16);
                ul.x = lw[0] | (lw[1] << 16); ul.y = lw[2] | (lw[3] << 16);
                ul.z = lw[4] | (lw[5] << 16); ul.w = lw[6] | (lw[7] << 16);
            }
            const int np = (t + 1) & 1;
            *(uint4*)((void*)(g_hh[np] + (size_t)b * H + nb)) = uh;
            *(uint4*)((void*)(g_hl[np] + (size_t)b * H + nb)) = ul;
        }

        grid_barrier();
    }

    // final states: h then c, each [B,H], appended after [B,T,H]
    if (tid < 64) {
        const int b = tid;
        float* oh = out + (size_t)M * H + (size_t)b * H + nb;
        float* oc = out + (size_t)M * H + (size_t)B * H + (size_t)b * H + nb;
        *(float4*)(oh)     = make_float4(hlast[0], hlast[1], hlast[2], hlast[3]);
        *(float4*)(oh + 4) = make_float4(hlast[4], hlast[5], hlast[6], hlast[7]);
        *(float4*)(oc)     = make_float4(creg[0], creg[1], creg[2], creg[3]);
        *(float4*)(oc + 4) = make_float4(creg[4], creg[5], creg[6], creg[7]);
    }
}

} // anonymous namespace

extern "C" void kernel_launch(void* const* d_in, const int* in_sizes, int n_in,
                              void* d_out, int out_size) {
    (void)in_sizes; (void)n_in; (void)out_size;
    const float* X    = (const float*)d_in[0];
    const float* W_f  = (const float*)d_in[1];
    const float* Wm_f = (const float*)d_in[2];
    const float* U_f  = (const float*)d_in[3];
    const float* Um_f = (const float*)d_in[4];
    const float* b_f  = (const float*)d_in[5];
    // inputs 6..10 (i-gate) are computed but unused by the reference -> skipped
    const float* W_o  = (const float*)d_in[11];
    const float* Wm_o = (const float*)d_in[12];
    const float* U_o  = (const float*)d_in[13];
    const float* Um_o = (const float*)d_in[14];
    const float* b_o  = (const float*)d_in[15];
    const float* W_c  = (const float*)d_in[16];
    const float* Wm_c = (const float*)d_in[17];
    const float* U_c  = (const float*)d_in[18];
    const float* Um_c = (const float*)d_in[19];
    const float* b_c  = (const float*)d_in[20];
    float* out = (float*)d_out;

    static int smem_set = 0;
    if (!smem_set) {
        cudaFuncSetAttribute(lstm_mma, cudaFuncAttributeMaxDynamicSharedMemorySize, LSMEM);
        smem_set = 1;
    }

    dim3 pg(H / BN, M / BM, 3);
    input_proj<<<pg, 128>>>(X, W_f, Wm_f, b_f, W_o, Wm_o, b_o, W_c, Wm_c, b_c);

    lstm_mma<<<128, 128, LSMEM>>>(U_f, Um_f, U_o, Um_o, U_c, Um_c, out);
}